// round 1
// baseline (speedup 1.0000x reference)
#include <cuda_runtime.h>
#include <math.h>

#define DIM_I 128
#define DIM_G 16
#define DIM_O 128
#define KTOT  (DIM_I * DIM_G * 2)   // 4096
#define BM 128
#define BN 128
#define BK 32                        // = 2*DIM_G, one input dim per K-iteration
#define TM 8
#define TN 8

// 2MB scratch for transposed, interleaved weights: Wt[k][o], k = i*32 + 2*g + {0=cos,1=sin}
__device__ float g_Wt[KTOT * DIM_O];

// ---------------------------------------------------------------------------
// packed f32x2 helpers (sm_103a)
// ---------------------------------------------------------------------------
__device__ __forceinline__ unsigned long long pack2(float lo, float hi) {
    unsigned long long r;
    asm("mov.b64 %0, {%1, %2};" : "=l"(r) : "f"(lo), "f"(hi));
    return r;
}
__device__ __forceinline__ void unpack2(unsigned long long v, float& lo, float& hi) {
    asm("mov.b64 {%0, %1}, %2;" : "=f"(lo), "=f"(hi) : "l"(v));
}
#define FMA2(d, a, b) \
    asm("fma.rn.f32x2 %0, %1, %2, %3;" : "=l"(d) : "l"(a), "l"(b), "l"(d))

// ---------------------------------------------------------------------------
// One-time weight transpose: cosA/sinA are (O, I, G) row-major.
// Wt[(i*32 + 2g + 0)*128 + o] = cosA[o,i,g]; (+1) = sinA[o,i,g]
// ---------------------------------------------------------------------------
__global__ void transpose_weights(const float* __restrict__ cosA,
                                  const float* __restrict__ sinA) {
    int t = blockIdx.x * blockDim.x + threadIdx.x;   // over O*I*G = 262144
    if (t >= DIM_O * DIM_I * DIM_G) return;
    int o = t / (DIM_I * DIM_G);
    int r = t % (DIM_I * DIM_G);
    int i = r / DIM_G;
    int g = r % DIM_G;
    int k = i * (2 * DIM_G) + 2 * g;
    g_Wt[(k + 0) * DIM_O + o] = cosA[t];
    g_Wt[(k + 1) * DIM_O + o] = sinA[t];
}

// ---------------------------------------------------------------------------
// Main fused kernel: feature-gen (trig recurrence) + GEMM (f32x2) + bias + LN
// ---------------------------------------------------------------------------
__global__ __launch_bounds__(256, 1)
void fkan_main(const float* __restrict__ X,
               const float* __restrict__ bias,
               const float* __restrict__ gamma,
               const float* __restrict__ beta,
               float* __restrict__ Out) {
    __shared__ float As[BK * BM];   // 4096 floats: As[j][n], j = 2g+{c,s}
    __shared__ float Bs[BK * BN];   // 4096 floats: Bs[j][o]

    const int tid = threadIdx.x;
    const int n0  = blockIdx.x * BM;
    const int tx  = tid & 15;       // o-tile index: o = tx*8 .. tx*8+7
    const int ty  = tid >> 4;       // n-tile index: n = ty*8 .. ty*8+7

    unsigned long long acc[TM][TN / 2];
    #pragma unroll
    for (int m = 0; m < TM; ++m)
        #pragma unroll
        for (int nn = 0; nn < TN / 2; ++nn)
            acc[m][nn] = 0ULL;

    for (int i = 0; i < DIM_I; ++i) {
        if (tid < 128) {
            // --- feature generation: row n = tid, input dim i ---
            float xv = X[(n0 + tid) * DIM_I + i];
            float s1, c1;
            sincosf(xv, &s1, &c1);
            float cg = c1, sg = s1;
            As[0 * BM + tid] = cg;
            As[1 * BM + tid] = sg;
            #pragma unroll
            for (int g = 1; g < DIM_G; ++g) {
                float cn = fmaf(cg, c1, -(sg * s1));   // cos((g+1)x)
                float sn = fmaf(sg, c1,  (cg * s1));   // sin((g+1)x)
                cg = cn; sg = sn;
                As[(2 * g)     * BM + tid] = cg;
                As[(2 * g + 1) * BM + tid] = sg;
            }
        } else {
            // --- weight tile load: 32x128 floats, fully coalesced float4 ---
            int t2 = tid - 128;
            const float4* src = (const float4*)(g_Wt + (size_t)i * (BK * BN));
            float4* dst = (float4*)Bs;
            #pragma unroll
            for (int r = 0; r < 8; ++r)
                dst[r * 128 + t2] = src[r * 128 + t2];
        }
        __syncthreads();

        #pragma unroll 8
        for (int j = 0; j < BK; ++j) {
            float4 a0 = *(const float4*)&As[j * BM + ty * TM];
            float4 a1 = *(const float4*)&As[j * BM + ty * TM + 4];
            ulonglong2 b0 = *(const ulonglong2*)&Bs[j * BN + tx * TN];
            ulonglong2 b1 = *(const ulonglong2*)&Bs[j * BN + tx * TN + 4];
            unsigned long long bv0 = b0.x, bv1 = b0.y, bv2 = b1.x, bv3 = b1.y;
            float av[8] = {a0.x, a0.y, a0.z, a0.w, a1.x, a1.y, a1.z, a1.w};
            #pragma unroll
            for (int m = 0; m < TM; ++m) {
                unsigned long long am = pack2(av[m], av[m]);
                FMA2(acc[m][0], am, bv0);
                FMA2(acc[m][1], am, bv1);
                FMA2(acc[m][2], am, bv2);
                FMA2(acc[m][3], am, bv3);
            }
        }
        __syncthreads();
    }

    // ------------------------------------------------------------------
    // Epilogue: bias + LayerNorm over O (=BN, entirely within this block)
    // ------------------------------------------------------------------
    float bi[8], ga[8], be[8];
    #pragma unroll
    for (int j = 0; j < 8; ++j) {
        int o = tx * 8 + j;
        bi[j] = bias[o];
        ga[j] = gamma[o];
        be[j] = beta[o];
    }

    // partial sums per (row, tx) into reused As
    float* redS = As;          // 128 rows * 16 = 2048 floats
    float* redQ = As + 2048;   // 2048 floats
    #pragma unroll
    for (int rr = 0; rr < TM; ++rr) {
        float s = 0.f, q = 0.f;
        #pragma unroll
        for (int nn = 0; nn < 4; ++nn) {
            float lo, hi;
            unpack2(acc[rr][nn], lo, hi);
            lo += bi[nn * 2];
            hi += bi[nn * 2 + 1];
            s += lo + hi;
            q += lo * lo + hi * hi;
        }
        int row = ty * TM + rr;
        redS[row * 16 + tx] = s;
        redQ[row * 16 + tx] = q;
    }
    __syncthreads();

    if (tid < 128) {
        float s = 0.f, q = 0.f;
        #pragma unroll
        for (int t = 0; t < 16; ++t) {
            s += redS[tid * 16 + t];
            q += redQ[tid * 16 + t];
        }
        float mu  = s * (1.0f / 128.0f);
        float var = q * (1.0f / 128.0f) - mu * mu;
        Bs[tid]       = mu;
        Bs[128 + tid] = rsqrtf(var + 1e-5f);
    }
    __syncthreads();

    #pragma unroll
    for (int rr = 0; rr < TM; ++rr) {
        int row  = ty * TM + rr;
        float mu = Bs[row];
        float rs = Bs[128 + row];
        float ov[8];
        #pragma unroll
        for (int nn = 0; nn < 4; ++nn) {
            float lo, hi;
            unpack2(acc[rr][nn], lo, hi);
            lo += bi[nn * 2];
            hi += bi[nn * 2 + 1];
            ov[nn * 2]     = (lo - mu) * rs * ga[nn * 2]     + be[nn * 2];
            ov[nn * 2 + 1] = (hi - mu) * rs * ga[nn * 2 + 1] + be[nn * 2 + 1];
        }
        float4* op = (float4*)&Out[(size_t)(n0 + row) * DIM_O + tx * 8];
        op[0] = make_float4(ov[0], ov[1], ov[2], ov[3]);
        op[1] = make_float4(ov[4], ov[5], ov[6], ov[7]);
    }
}

// ---------------------------------------------------------------------------
// Launch: inputs in metadata order: x, cos_amplitudes, sin_amplitudes,
//         bias, ln_gamma, ln_beta. Output fp32 (N, O).
// ---------------------------------------------------------------------------
extern "C" void kernel_launch(void* const* d_in, const int* in_sizes, int n_in,
                              void* d_out, int out_size) {
    const float* x     = (const float*)d_in[0];
    const float* cosA  = (const float*)d_in[1];
    const float* sinA  = (const float*)d_in[2];
    const float* bias  = (const float*)d_in[3];
    const float* gamma = (const float*)d_in[4];
    const float* beta  = (const float*)d_in[5];
    float* out = (float*)d_out;

    int N = in_sizes[0] / DIM_I;

    int tw_items  = DIM_O * DIM_I * DIM_G;
    transpose_weights<<<(tw_items + 255) / 256, 256>>>(cosA, sinA);
    fkan_main<<<N / BM, 256>>>(x, bias, gamma, beta, out);
}

// round 3
// speedup vs baseline: 2.7849x; 2.7849x over previous
#include <cuda_runtime.h>
#include <cuda_bf16.h>
#include <math.h>
#include <stdint.h>

#define DIM_I 128
#define DIM_G 16
#define DIM_O 128
#define NCHUNKS 64              // chunk = 2 input dims = 64 k-steps
#define PLANE 16384             // 128 rows x 64 bf16 (128B rows)
#define CHUNK_BYTES 32768       // hi plane + lo plane (B in global, per chunk)

// Pre-split (bf16 hi/lo), pre-swizzled weights: [chunk][Bhi 16K][Blo 16K]
__device__ __align__(16) unsigned char g_B[NCHUNKS * CHUNK_BYTES];   // 2 MB

// ---- dynamic SMEM layout ----
// buf: [Ahi 16K | Alo 16K | Bhi 16K | Blo 16K] = 64KB, double buffered
#define SM_BUF0 0
#define SM_BUF1 65536
#define SM_PAR  131072                       // bias|gamma|beta 3*128 f32
#define SMEM_TOTAL (SM_PAR + 3 * 128 * 4)    // 132608
#define EPI_STRIDE 132                       // epilogue f32 tile reuses buf region

__device__ __forceinline__ uint32_t smem_u32(const void* p) {
    uint32_t a;
    asm("{ .reg .u64 t; cvta.to.shared.u64 t, %1; cvt.u32.u64 %0, t; }" : "=r"(a) : "l"(p));
    return a;
}
__device__ __forceinline__ void ldsm4(uint32_t& r0, uint32_t& r1, uint32_t& r2,
                                      uint32_t& r3, uint32_t a) {
    asm volatile("ldmatrix.sync.aligned.m8n8.x4.shared.b16 {%0,%1,%2,%3}, [%4];"
                 : "=r"(r0), "=r"(r1), "=r"(r2), "=r"(r3) : "r"(a));
}
__device__ __forceinline__ void mma16816(float* d, const uint32_t* a, const uint32_t* b) {
    asm volatile(
        "mma.sync.aligned.m16n8k16.row.col.f32.bf16.bf16.f32 "
        "{%0,%1,%2,%3}, {%4,%5,%6,%7}, {%8,%9}, {%0,%1,%2,%3};"
        : "+f"(d[0]), "+f"(d[1]), "+f"(d[2]), "+f"(d[3])
        : "r"(a[0]), "r"(a[1]), "r"(a[2]), "r"(a[3]), "r"(b[0]), "r"(b[1]));
}
#define CP_ASYNC16(dst, src) \
    asm volatile("cp.async.cg.shared.global [%0], [%1], 16;" :: "r"(dst), "l"(src) : "memory")
#define CP_COMMIT()  asm volatile("cp.async.commit_group;" ::: "memory")
#define CP_WAIT0()   asm volatile("cp.async.wait_group 0;" ::: "memory")

// ---------------------------------------------------------------------------
// Prep: split weights to bf16 hi(trunc)+lo(rn residual), arrange [n=o][k] rows
// of 128B with XOR-swizzle (16B chunk c ^= (n&7)), per 64-k chunk.
// k_local = (i&1)*32 + 2g + {0=cos,1=sin}; chunk = i>>1.
// ---------------------------------------------------------------------------
__global__ void prep_weights(const float* __restrict__ cosA,
                             const float* __restrict__ sinA) {
    int t = blockIdx.x * blockDim.x + threadIdx.x;   // over O*I*G = 262144
    if (t >= DIM_O * DIM_I * DIM_G) return;
    int o = t >> 11, rem = t & 2047, i = rem >> 4, g = rem & 15;
    float cv = cosA[t], sv = sinA[t];
    uint32_t cb = __float_as_uint(cv), sbv = __float_as_uint(sv);
    uint32_t hiw = __byte_perm(cb, sbv, 0x7632);     // {cos_hi16, sin_hi16}
    float lc = cv - __uint_as_float(cb & 0xFFFF0000u);
    float ls = sv - __uint_as_float(sbv & 0xFFFF0000u);
    uint32_t low;
    asm("cvt.rn.bf16x2.f32 %0, %1, %2;" : "=r"(low) : "f"(ls), "f"(lc));
    int chunk = i >> 1;
    int kl = (i & 1) * 32 + 2 * g;                   // even
    int cidx = kl >> 3;
    uint32_t off = (uint32_t)(o * 128 + ((cidx ^ (o & 7)) << 4) + (kl & 7) * 2);
    *(uint32_t*)(g_B + (size_t)chunk * CHUNK_BYTES + off) = hiw;
    *(uint32_t*)(g_B + (size_t)chunk * CHUNK_BYTES + PLANE + off) = low;
}

// ---------------------------------------------------------------------------
// Main: trig-recurrence feature gen (bf16 hi/lo) + 3-pass bf16 mma.sync GEMM
// + fused bias + LayerNorm epilogue. BM=128, BN=128(=O), 256 threads.
// ---------------------------------------------------------------------------
__global__ __launch_bounds__(256, 1)
void fkan_hmma(const float* __restrict__ X,
               const float* __restrict__ bias,
               const float* __restrict__ gamma,
               const float* __restrict__ beta,
               float* __restrict__ Out) {
    extern __shared__ unsigned char smem[];
    const uint32_t sb = smem_u32(smem);
    const int tid = threadIdx.x, w = tid >> 5, lane = tid & 31;
    const int n0blk = blockIdx.x * 128;

    if (tid < 128) {
        ((float*)(smem + SM_PAR))[tid]       = bias[tid];
        ((float*)(smem + SM_PAR))[128 + tid] = gamma[tid];
        ((float*)(smem + SM_PAR))[256 + tid] = beta[tid];
    }

    // ---- feature-gen constants: thread = (row, half-dim) ----
    const int row = tid & 127, hd = tid >> 7;
    const size_t xrow_off = (size_t)(n0blk + row) * DIM_I;
    uint32_t aoff[4];
    #pragma unroll
    for (int q = 0; q < 4; ++q)
        aoff[q] = (uint32_t)(row * 128 + (((hd * 4 + q) ^ (row & 7)) << 4));

    // ---- mma constants: warps 4m x 2n, warp tile 32m x 64n ----
    const int m0w = (w >> 1) * 32, nn0w = (w & 1) * 64;
    const int r8 = lane & 7, bsel = lane >> 3;
    const int kbA = bsel >> 1;                         // A block k-half
    const int mr0 = m0w + r8 + ((bsel & 1) << 3);
    const uint32_t mo0 = (uint32_t)(mr0 * 128), mo1 = mo0 + 16 * 128;
    const uint32_t mswA = (uint32_t)(mr0 & 7);
    const int kbB = bsel & 1;                          // B block k-half
    const int nrb = nn0w + r8 + ((bsel >> 1) << 3);
    const uint32_t nswB = (uint32_t)(nrb & 7);
    uint32_t no[4];
    #pragma unroll
    for (int pt = 0; pt < 4; ++pt) no[pt] = (uint32_t)((nrb + pt * 16) * 128);

    float acc[2][8][4];
    #pragma unroll
    for (int mt = 0; mt < 2; ++mt)
        #pragma unroll
        for (int nt = 0; nt < 8; ++nt)
            #pragma unroll
            for (int j = 0; j < 4; ++j) acc[mt][nt][j] = 0.f;

    // ---- helpers as lambdas ----
    auto cpasyncB = [&](int c, uint32_t bufoff) {
        const unsigned char* gsrc = g_B + (size_t)c * CHUNK_BYTES;
        #pragma unroll
        for (int j = 0; j < 8; ++j) {
            uint32_t idx = (uint32_t)(tid + j * 256) * 16u;
            CP_ASYNC16(sb + bufoff + 32768u + idx, gsrc + idx);
        }
        CP_COMMIT();
    };
    auto genA = [&](int c, uint32_t bufoff) {
        const int dim = 2 * c + hd;
        float xv = X[xrow_off + dim];
        float s1, c1;
        sincosf(xv, &s1, &c1);
        uint32_t hi[16], lo[16];
        float cg = c1, sg = s1;
        #pragma unroll
        for (int g = 0; g < 16; ++g) {
            if (g) {
                float cn = fmaf(cg, c1, -(sg * s1));
                float sn = fmaf(sg, c1,  (cg * s1));
                cg = cn; sg = sn;
            }
            uint32_t cb = __float_as_uint(cg), sbv = __float_as_uint(sg);
            hi[g] = __byte_perm(cb, sbv, 0x7632);
            float lc = cg - __uint_as_float(cb  & 0xFFFF0000u);
            float ls = sg - __uint_as_float(sbv & 0xFFFF0000u);
            asm("cvt.rn.bf16x2.f32 %0, %1, %2;" : "=r"(lo[g]) : "f"(ls), "f"(lc));
        }
        #pragma unroll
        for (int q = 0; q < 4; ++q) {
            *(uint4*)(smem + bufoff + aoff[q]) =
                make_uint4(hi[4*q], hi[4*q+1], hi[4*q+2], hi[4*q+3]);
            *(uint4*)(smem + bufoff + PLANE + aoff[q]) =
                make_uint4(lo[4*q], lo[4*q+1], lo[4*q+2], lo[4*q+3]);
        }
    };
    auto mmaChunk = [&](uint32_t bufoff) {
        const uint32_t AH = sb + bufoff, AL = AH + PLANE;
        const uint32_t BH = AH + 2 * PLANE, BL = AH + 3 * PLANE;
        #pragma unroll
        for (int ks = 0; ks < 4; ++ks) {
            const uint32_t kxA = (uint32_t)(((ks << 1) | kbA) ^ mswA) << 4;
            const uint32_t kxB = (uint32_t)(((ks << 1) | kbB) ^ nswB) << 4;
            uint32_t ah0[4], ah1[4], al0[4], al1[4], bhf[16], blf[16];
            ldsm4(ah0[0], ah0[1], ah0[2], ah0[3], AH + mo0 + kxA);
            ldsm4(ah1[0], ah1[1], ah1[2], ah1[3], AH + mo1 + kxA);
            ldsm4(al0[0], al0[1], al0[2], al0[3], AL + mo0 + kxA);
            ldsm4(al1[0], al1[1], al1[2], al1[3], AL + mo1 + kxA);
            #pragma unroll
            for (int pt = 0; pt < 4; ++pt) {
                ldsm4(bhf[4*pt], bhf[4*pt+1], bhf[4*pt+2], bhf[4*pt+3], BH + no[pt] + kxB);
                ldsm4(blf[4*pt], blf[4*pt+1], blf[4*pt+2], blf[4*pt+3], BL + no[pt] + kxB);
            }
            #pragma unroll
            for (int nt = 0; nt < 8; ++nt) {
                const uint32_t* bh = &bhf[(nt >> 1) * 4 + (nt & 1) * 2];
                mma16816(acc[0][nt], ah0, bh);
                mma16816(acc[1][nt], ah1, bh);
            }
            #pragma unroll
            for (int nt = 0; nt < 8; ++nt) {
                const uint32_t* bh = &bhf[(nt >> 1) * 4 + (nt & 1) * 2];
                mma16816(acc[0][nt], al0, bh);
                mma16816(acc[1][nt], al1, bh);
            }
            #pragma unroll
            for (int nt = 0; nt < 8; ++nt) {
                const uint32_t* bl = &blf[(nt >> 1) * 4 + (nt & 1) * 2];
                mma16816(acc[0][nt], ah0, bl);
                mma16816(acc[1][nt], ah1, bl);
            }
        }
    };

    // ---- prologue: stage chunk 0 ----
    cpasyncB(0, SM_BUF0);
    genA(0, SM_BUF0);
    CP_WAIT0();
    __syncthreads();

    // ---- main pipelined loop ----
    for (int c = 0; c < NCHUNKS; ++c) {
        const uint32_t bufc = (c & 1) ? SM_BUF1 : SM_BUF0;
        const uint32_t bufn = (c & 1) ? SM_BUF0 : SM_BUF1;
        if (c < NCHUNKS - 1) {
            cpasyncB(c + 1, bufn);
            genA(c + 1, bufn);
        }
        mmaChunk(bufc);
        if (c < NCHUNKS - 1) CP_WAIT0();
        __syncthreads();
    }

    // ---- epilogue: acc -> smem f32 tile (stride 132), then bias + LN ----
    {
        float* tile = (float*)smem;                  // reuse buffers (67584B < 128KB)
        const int g4 = lane >> 2, t4 = lane & 3;
        #pragma unroll
        for (int mt = 0; mt < 2; ++mt) {
            #pragma unroll
            for (int nt = 0; nt < 8; ++nt) {
                int rowm = m0w + mt * 16 + g4;
                int col  = nn0w + nt * 8 + 2 * t4;
                *(float2*)&tile[rowm * EPI_STRIDE + col] =
                    make_float2(acc[mt][nt][0], acc[mt][nt][1]);
                *(float2*)&tile[(rowm + 8) * EPI_STRIDE + col] =
                    make_float2(acc[mt][nt][2], acc[mt][nt][3]);
            }
        }
    }
    __syncthreads();

    if (tid < 128) {
        const float* tile = (const float*)smem;
        const float* bS  = (const float*)(smem + SM_PAR);
        const float* gS  = bS + 128;
        const float* btS = bS + 256;
        float v[128];
        float s = 0.f, q = 0.f;
        #pragma unroll
        for (int j4 = 0; j4 < 32; ++j4) {
            float4 t4v = *(const float4*)&tile[tid * EPI_STRIDE + j4 * 4];
            float a0 = t4v.x + bS[j4*4+0], a1 = t4v.y + bS[j4*4+1];
            float a2 = t4v.z + bS[j4*4+2], a3 = t4v.w + bS[j4*4+3];
            v[j4*4+0] = a0; v[j4*4+1] = a1; v[j4*4+2] = a2; v[j4*4+3] = a3;
            s += (a0 + a1) + (a2 + a3);
            q += a0*a0 + a1*a1 + a2*a2 + a3*a3;
        }
        float mu  = s * (1.0f / 128.0f);
        float var = q * (1.0f / 128.0f) - mu * mu;
        float rs  = rsqrtf(var + 1e-5f);
        float4* op = (float4*)(Out + (size_t)(n0blk + tid) * DIM_O);
        #pragma unroll
        for (int j4 = 0; j4 < 32; ++j4) {
            float4 o;
            o.x = (v[j4*4+0] - mu) * rs * gS[j4*4+0] + btS[j4*4+0];
            o.y = (v[j4*4+1] - mu) * rs * gS[j4*4+1] + btS[j4*4+1];
            o.z = (v[j4*4+2] - mu) * rs * gS[j4*4+2] + btS[j4*4+2];
            o.w = (v[j4*4+3] - mu) * rs * gS[j4*4+3] + btS[j4*4+3];
            op[j4] = o;
        }
    }
}

// ---------------------------------------------------------------------------
extern "C" void kernel_launch(void* const* d_in, const int* in_sizes, int n_in,
                              void* d_out, int out_size) {
    const float* x     = (const float*)d_in[0];
    const float* cosA  = (const float*)d_in[1];
    const float* sinA  = (const float*)d_in[2];
    const float* bias  = (const float*)d_in[3];
    const float* gamma = (const float*)d_in[4];
    const float* beta  = (const float*)d_in[5];
    float* out = (float*)d_out;

    const int N = in_sizes[0] / DIM_I;

    cudaFuncSetAttribute(fkan_hmma, cudaFuncAttributeMaxDynamicSharedMemorySize,
                         SMEM_TOTAL);

    const int tw = DIM_O * DIM_I * DIM_G;
    prep_weights<<<(tw + 255) / 256, 256>>>(cosA, sinA);
    fkan_hmma<<<N / 128, 256, SMEM_TOTAL>>>(x, bias, gamma, beta, out);
}

// round 4
// speedup vs baseline: 3.8432x; 1.3800x over previous
#include <cuda_runtime.h>
#include <cuda_fp16.h>
#include <math.h>
#include <stdint.h>

#define DIM_I 128
#define DIM_G 16
#define DIM_O 128
#define NCHUNKS 64              // chunk = 2 input dims = 64 k-steps
#define PLANE 16384             // 128 rows x 64 fp16 (128B rows)

// Pre-converted fp16 weights, pre-swizzled, one plane per chunk
__device__ __align__(16) unsigned char g_B[NCHUNKS * PLANE];   // 1 MB

// ---- dynamic SMEM: buf = [Ahi 16K | Alo 16K | B 16K] = 48KB, double buffered
#define BUF_BYTES  (3 * PLANE)
#define SM_BUF0 0
#define SM_BUF1 BUF_BYTES                        // 49152
#define SM_PAR  (2 * BUF_BYTES)                  // 98304 ; bias|gamma|beta
#define SMEM_TOTAL (SM_PAR + 3 * 128 * 4)        // 99840
#define EPI_STRIDE 132                           // 33 float4 -> conflict-free

__device__ __forceinline__ uint32_t smem_u32(const void* p) {
    uint32_t a;
    asm("{ .reg .u64 t; cvta.to.shared.u64 t, %1; cvt.u32.u64 %0, t; }" : "=r"(a) : "l"(p));
    return a;
}
__device__ __forceinline__ void ldsm4(uint32_t& r0, uint32_t& r1, uint32_t& r2,
                                      uint32_t& r3, uint32_t a) {
    asm volatile("ldmatrix.sync.aligned.m8n8.x4.shared.b16 {%0,%1,%2,%3}, [%4];"
                 : "=r"(r0), "=r"(r1), "=r"(r2), "=r"(r3) : "r"(a));
}
__device__ __forceinline__ void mma16816(float* d, const uint32_t* a, const uint32_t* b) {
    asm volatile(
        "mma.sync.aligned.m16n8k16.row.col.f32.f16.f16.f32 "
        "{%0,%1,%2,%3}, {%4,%5,%6,%7}, {%8,%9}, {%0,%1,%2,%3};"
        : "+f"(d[0]), "+f"(d[1]), "+f"(d[2]), "+f"(d[3])
        : "r"(a[0]), "r"(a[1]), "r"(a[2]), "r"(a[3]), "r"(b[0]), "r"(b[1]));
}
#define CP_ASYNC16(dst, src) \
    asm volatile("cp.async.cg.shared.global [%0], [%1], 16;" :: "r"(dst), "l"(src) : "memory")
#define CP_COMMIT()  asm volatile("cp.async.commit_group;" ::: "memory")
#define CP_WAIT0()   asm volatile("cp.async.wait_group 0;" ::: "memory")

// ---------------------------------------------------------------------------
// Prep: weights -> fp16, {cos,sin} adjacent in k, swizzled 128B rows per chunk.
// k_local = (i&1)*32 + 2g + {0=cos,1=sin}; chunk = i>>1.
// ---------------------------------------------------------------------------
__global__ void prep_weights(const float* __restrict__ cosA,
                             const float* __restrict__ sinA) {
    int t = blockIdx.x * blockDim.x + threadIdx.x;   // over O*I*G = 262144
    if (t >= DIM_O * DIM_I * DIM_G) return;
    int o = t >> 11, rem = t & 2047, i = rem >> 4, g = rem & 15;
    half2 w = __floats2half2_rn(cosA[t], sinA[t]);   // lo=cos, hi=sin
    int chunk = i >> 1;
    int kl = (i & 1) * 32 + 2 * g;
    int cidx = kl >> 3;
    uint32_t off = (uint32_t)(o * 128 + ((cidx ^ (o & 7)) << 4) + (kl & 7) * 2);
    *(uint32_t*)(g_B + (size_t)chunk * PLANE + off) = *(uint32_t*)&w;
}

// ---------------------------------------------------------------------------
// Main: trig recurrence -> fp16 hi/lo A planes; B single fp16 plane (cp.async);
// 2-pass mma.sync fp16 GEMM; fused bias + LayerNorm. 512 threads, BM=BN=128.
// ---------------------------------------------------------------------------
__global__ __launch_bounds__(512, 1)
void fkan_hmma(const float* __restrict__ X,
               const float* __restrict__ bias,
               const float* __restrict__ gamma,
               const float* __restrict__ beta,
               float* __restrict__ Out) {
    extern __shared__ unsigned char smem[];
    const uint32_t sb = smem_u32(smem);
    const int tid = threadIdx.x, w = tid >> 5, lane = tid & 31;
    const int n0blk = blockIdx.x * 128;

    if (tid < 128) {
        ((float*)(smem + SM_PAR))[tid]       = bias[tid];
        ((float*)(smem + SM_PAR))[128 + tid] = gamma[tid];
        ((float*)(smem + SM_PAR))[256 + tid] = beta[tid];
    }

    // ---- producer roles: warps 0-7 gen A, warps 8-15 cp.async B ----
    const int row = tid & 127, hd = (tid >> 7) & 1;  // meaningful for tid<256
    const size_t xrow_off = (size_t)(n0blk + row) * DIM_I;
    uint32_t aoff[4];
    #pragma unroll
    for (int q = 0; q < 4; ++q)
        aoff[q] = (uint32_t)(row * 128 + (((hd * 4 + q) ^ (row & 7)) << 4));

    // ---- mma constants: 16 warps as 8m x 2n, warp tile 16m x 64n ----
    const int m0w = (w >> 1) * 16, nn0w = (w & 1) * 64;
    const int r8 = lane & 7, bsel = lane >> 3;
    const int kbA = bsel >> 1;
    const int mr0 = m0w + r8 + ((bsel & 1) << 3);
    const uint32_t mo0 = (uint32_t)(mr0 * 128);
    const uint32_t mswA = (uint32_t)(mr0 & 7);
    const int kbB = bsel & 1;
    const int nrb = nn0w + r8 + ((bsel >> 1) << 3);
    const uint32_t nswB = (uint32_t)(nrb & 7);
    uint32_t no[4];
    #pragma unroll
    for (int pt = 0; pt < 4; ++pt) no[pt] = (uint32_t)((nrb + pt * 16) * 128);

    float acc[8][4];
    #pragma unroll
    for (int nt = 0; nt < 8; ++nt)
        #pragma unroll
        for (int j = 0; j < 4; ++j) acc[nt][j] = 0.f;

    auto produce = [&](int c, uint32_t bufoff) {
        if (tid < 256) {
            // feature gen: (row, half-dim) -> 16 hi words + 16 lo words
            const int dim = 2 * c + hd;
            float xv = X[xrow_off + dim];
            float s1, c1;
            sincosf(xv, &s1, &c1);
            uint32_t hi[16], lo[16];
            float cg = c1, sg = s1;
            #pragma unroll
            for (int g = 0; g < 16; ++g) {
                if (g) {
                    float cn = fmaf(cg, c1, -(sg * s1));
                    float sn = fmaf(sg, c1,  (cg * s1));
                    cg = cn; sg = sn;
                }
                half2 h = __floats2half2_rn(cg, sg);
                hi[g] = *(uint32_t*)&h;
                float lc = cg - __low2float(h);
                float ls = sg - __high2float(h);
                half2 l = __floats2half2_rn(lc, ls);
                lo[g] = *(uint32_t*)&l;
            }
            #pragma unroll
            for (int q = 0; q < 4; ++q) {
                *(uint4*)(smem + bufoff + aoff[q]) =
                    make_uint4(hi[4*q], hi[4*q+1], hi[4*q+2], hi[4*q+3]);
                *(uint4*)(smem + bufoff + PLANE + aoff[q]) =
                    make_uint4(lo[4*q], lo[4*q+1], lo[4*q+2], lo[4*q+3]);
            }
        } else {
            const unsigned char* gsrc = g_B + (size_t)c * PLANE;
            const int t2 = tid - 256;
            #pragma unroll
            for (int j = 0; j < 4; ++j) {
                uint32_t idx = (uint32_t)(t2 + j * 256) * 16u;
                CP_ASYNC16(sb + bufoff + 2u * PLANE + idx, gsrc + idx);
            }
            CP_COMMIT();
        }
    };
    auto mmaChunk = [&](uint32_t bufoff) {
        const uint32_t AH = sb + bufoff, AL = AH + PLANE, BP = AH + 2 * PLANE;
        #pragma unroll
        for (int ks = 0; ks < 4; ++ks) {
            const uint32_t kxA = (uint32_t)(((ks << 1) | kbA) ^ mswA) << 4;
            const uint32_t kxB = (uint32_t)(((ks << 1) | kbB) ^ nswB) << 4;
            uint32_t ah[4], al[4], bf[16];
            ldsm4(ah[0], ah[1], ah[2], ah[3], AH + mo0 + kxA);
            ldsm4(al[0], al[1], al[2], al[3], AL + mo0 + kxA);
            #pragma unroll
            for (int pt = 0; pt < 4; ++pt)
                ldsm4(bf[4*pt], bf[4*pt+1], bf[4*pt+2], bf[4*pt+3], BP + no[pt] + kxB);
            #pragma unroll
            for (int nt = 0; nt < 8; ++nt) {
                const uint32_t* b = &bf[(nt >> 1) * 4 + (nt & 1) * 2];
                mma16816(acc[nt], ah, b);
            }
            #pragma unroll
            for (int nt = 0; nt < 8; ++nt) {
                const uint32_t* b = &bf[(nt >> 1) * 4 + (nt & 1) * 2];
                mma16816(acc[nt], al, b);
            }
        }
    };

    // ---- prologue ----
    produce(0, SM_BUF0);
    CP_WAIT0();
    __syncthreads();

    // ---- main pipelined loop ----
    for (int c = 0; c < NCHUNKS; ++c) {
        const uint32_t bufc = (c & 1) ? SM_BUF1 : SM_BUF0;
        const uint32_t bufn = (c & 1) ? SM_BUF0 : SM_BUF1;
        if (c < NCHUNKS - 1) produce(c + 1, bufn);
        mmaChunk(bufc);
        if (c < NCHUNKS - 1) CP_WAIT0();
        __syncthreads();
    }

    // ---- epilogue: acc -> f32 smem tile -> bias + LN -> gmem ----
    {
        float* tile = (float*)smem;                  // reuse buffers (67584B)
        const int g4 = lane >> 2, t4 = lane & 3;
        #pragma unroll
        for (int nt = 0; nt < 8; ++nt) {
            int rowm = m0w + g4;
            int col  = nn0w + nt * 8 + 2 * t4;
            *(float2*)&tile[rowm * EPI_STRIDE + col] = make_float2(acc[nt][0], acc[nt][1]);
            *(float2*)&tile[(rowm + 8) * EPI_STRIDE + col] = make_float2(acc[nt][2], acc[nt][3]);
        }
    }
    __syncthreads();

    if (tid < 128) {
        const float* tile = (const float*)smem;
        const float* bS  = (const float*)(smem + SM_PAR);
        const float* gS  = bS + 128;
        const float* btS = bS + 256;
        float v[128];
        float s = 0.f, q = 0.f;
        #pragma unroll
        for (int j4 = 0; j4 < 32; ++j4) {
            float4 t4v = *(const float4*)&tile[tid * EPI_STRIDE + j4 * 4];
            float a0 = t4v.x + bS[j4*4+0], a1 = t4v.y + bS[j4*4+1];
            float a2 = t4v.z + bS[j4*4+2], a3 = t4v.w + bS[j4*4+3];
            v[j4*4+0] = a0; v[j4*4+1] = a1; v[j4*4+2] = a2; v[j4*4+3] = a3;
            s += (a0 + a1) + (a2 + a3);
            q += a0*a0 + a1*a1 + a2*a2 + a3*a3;
        }
        float mu  = s * (1.0f / 128.0f);
        float var = q * (1.0f / 128.0f) - mu * mu;
        float rs  = rsqrtf(var + 1e-5f);
        float4* op = (float4*)(Out + (size_t)(n0blk + tid) * DIM_O);
        #pragma unroll
        for (int j4 = 0; j4 < 32; ++j4) {
            float4 o;
            o.x = (v[j4*4+0] - mu) * rs * gS[j4*4+0] + btS[j4*4+0];
            o.y = (v[j4*4+1] - mu) * rs * gS[j4*4+1] + btS[j4*4+1];
            o.z = (v[j4*4+2] - mu) * rs * gS[j4*4+2] + btS[j4*4+2];
            o.w = (v[j4*4+3] - mu) * rs * gS[j4*4+3] + btS[j4*4+3];
            op[j4] = o;
        }
    }
}

// ---------------------------------------------------------------------------
extern "C" void kernel_launch(void* const* d_in, const int* in_sizes, int n_in,
                              void* d_out, int out_size) {
    const float* x     = (const float*)d_in[0];
    const float* cosA  = (const float*)d_in[1];
    const float* sinA  = (const float*)d_in[2];
    const float* bias  = (const float*)d_in[3];
    const float* gamma = (const float*)d_in[4];
    const float* beta  = (const float*)d_in[5];
    float* out = (float*)d_out;

    const int N = in_sizes[0] / DIM_I;

    cudaFuncSetAttribute(fkan_hmma, cudaFuncAttributeMaxDynamicSharedMemorySize,
                         SMEM_TOTAL);

    const int tw = DIM_O * DIM_I * DIM_G;
    prep_weights<<<(tw + 255) / 256, 256>>>(cosA, sinA);
    fkan_hmma<<<N / 128, 512, SMEM_TOTAL>>>(x, bias, gamma, beta, out);
}

// round 5
// speedup vs baseline: 6.1906x; 1.6108x over previous
#include <cuda_runtime.h>
#include <cuda_fp16.h>
#include <stdint.h>

#define DIM_I 128
#define DIM_G 16
#define DIM_O 128
#define NCHUNKS 64               // chunk = 2 input dims = 64 k-steps
#define B_BYTES 16384            // 128 o-rows x 64 fp16 (128B rows)
#define A_BYTES 8192             // 64 rows x 64 fp16
#define BUF_BYTES (A_BYTES + B_BYTES)        // 24576
#define SM_BUF0 0
#define SM_BUF1 BUF_BYTES
#define SM_PAR  (2 * BUF_BYTES)              // 49152 ; bias|gamma|beta
#define SMEM_TOTAL (SM_PAR + 3 * 128 * 4)    // 50688
#define EPI_STRIDE 132

// Pre-converted fp16 weights, pre-swizzled, one plane per chunk
__device__ __align__(16) unsigned char g_B[NCHUNKS * B_BYTES];   // 1 MB

__device__ __forceinline__ uint32_t smem_u32(const void* p) {
    uint32_t a;
    asm("{ .reg .u64 t; cvta.to.shared.u64 t, %1; cvt.u32.u64 %0, t; }" : "=r"(a) : "l"(p));
    return a;
}
__device__ __forceinline__ void ldsm4(uint32_t& r0, uint32_t& r1, uint32_t& r2,
                                      uint32_t& r3, uint32_t a) {
    asm volatile("ldmatrix.sync.aligned.m8n8.x4.shared.b16 {%0,%1,%2,%3}, [%4];"
                 : "=r"(r0), "=r"(r1), "=r"(r2), "=r"(r3) : "r"(a));
}
__device__ __forceinline__ void mma16816(float* d, const uint32_t* a, const uint32_t* b) {
    asm volatile(
        "mma.sync.aligned.m16n8k16.row.col.f32.f16.f16.f32 "
        "{%0,%1,%2,%3}, {%4,%5,%6,%7}, {%8,%9}, {%0,%1,%2,%3};"
        : "+f"(d[0]), "+f"(d[1]), "+f"(d[2]), "+f"(d[3])
        : "r"(a[0]), "r"(a[1]), "r"(a[2]), "r"(a[3]), "r"(b[0]), "r"(b[1]));
}
#define CP_ASYNC16(dst, src) \
    asm volatile("cp.async.cg.shared.global [%0], [%1], 16;" :: "r"(dst), "l"(src) : "memory")
#define CP_COMMIT()  asm volatile("cp.async.commit_group;" ::: "memory")
#define CP_WAIT0()   asm volatile("cp.async.wait_group 0;" ::: "memory")

// ---------------------------------------------------------------------------
// Prep: weights -> fp16, {cos,sin} adjacent in k, swizzled 128B rows per chunk.
// k_local = (i&1)*32 + 2g + {0=cos,1=sin}; chunk = i>>1.
// ---------------------------------------------------------------------------
__global__ void prep_weights(const float* __restrict__ cosA,
                             const float* __restrict__ sinA) {
    int t = blockIdx.x * blockDim.x + threadIdx.x;   // over O*I*G = 262144
    if (t >= DIM_O * DIM_I * DIM_G) return;
    int o = t >> 11, rem = t & 2047, i = rem >> 4, g = rem & 15;
    half2 w = __floats2half2_rn(cosA[t], sinA[t]);   // lo=cos, hi=sin
    int chunk = i >> 1;
    int kl = (i & 1) * 32 + 2 * g;
    int cidx = kl >> 3;
    uint32_t off = (uint32_t)(o * 128 + ((cidx ^ (o & 7)) << 4) + (kl & 7) * 2);
    *(uint32_t*)(g_B + (size_t)chunk * B_BYTES + off) = *(uint32_t*)&w;
}

// ---------------------------------------------------------------------------
// Main: BM=64, BN=128, 256 threads, 2 CTAs/SM. Single-pass fp16 mma.sync GEMM
// with on-the-fly trig features; fused bias + LayerNorm.
// ---------------------------------------------------------------------------
__global__ __launch_bounds__(256, 2)
void fkan_hmma(const float* __restrict__ X,
               const float* __restrict__ bias,
               const float* __restrict__ gamma,
               const float* __restrict__ beta,
               float* __restrict__ Out) {
    extern __shared__ unsigned char smem[];
    const uint32_t sb = smem_u32(smem);
    const int tid = threadIdx.x, w = tid >> 5, lane = tid & 31;
    const int n0blk = blockIdx.x * 64;

    if (tid < 128) {
        ((float*)(smem + SM_PAR))[tid]       = bias[tid];
        ((float*)(smem + SM_PAR))[128 + tid] = gamma[tid];
        ((float*)(smem + SM_PAR))[256 + tid] = beta[tid];
    }

    // ---- producer roles: warps 0-3 gen A (64 rows x 2 dims), warps 4-7 cp B ----
    const int row = tid & 63, hd = (tid >> 6) & 1;   // meaningful for tid<128
    const size_t xrow_off = (size_t)(n0blk + row) * DIM_I;
    uint32_t aoff[4];
    #pragma unroll
    for (int q = 0; q < 4; ++q)
        aoff[q] = (uint32_t)(row * 128 + (((hd * 4 + q) ^ (row & 7)) << 4));

    // ---- mma constants: 8 warps as 2m x 4n, warp tile 32m x 32n ----
    const int m0w = (w >> 2) * 32, nb = (w & 3) * 32;
    const int r8 = lane & 7, bsel = lane >> 3;
    const int kbA = bsel >> 1;
    const int mr0 = m0w + r8 + ((bsel & 1) << 3);
    const uint32_t moA0 = (uint32_t)(mr0 * 128), moA1 = moA0 + 16 * 128;
    const uint32_t mswA = (uint32_t)(mr0 & 7);
    const int kbB = bsel & 1;
    const int nrb = nb + r8 + ((bsel >> 1) << 3);
    const uint32_t nswB = (uint32_t)(nrb & 7);
    const uint32_t noB0 = (uint32_t)(nrb * 128), noB1 = noB0 + 16 * 128;

    float acc[2][4][4];
    #pragma unroll
    for (int mt = 0; mt < 2; ++mt)
        #pragma unroll
        for (int nt = 0; nt < 4; ++nt)
            #pragma unroll
            for (int j = 0; j < 4; ++j) acc[mt][nt][j] = 0.f;

    auto produce = [&](int c, uint32_t bufoff) {
        if (tid < 128) {
            const int dim = 2 * c + hd;
            float xv = X[xrow_off + dim];
            float s1, c1;
            __sincosf(xv, &s1, &c1);
            uint32_t hv[16];
            float cg = c1, sg = s1;
            #pragma unroll
            for (int g = 0; g < 16; ++g) {
                if (g) {
                    float cn = fmaf(cg, c1, -(sg * s1));
                    float sn = fmaf(sg, c1,  (cg * s1));
                    cg = cn; sg = sn;
                }
                half2 h = __floats2half2_rn(cg, sg);
                hv[g] = *(uint32_t*)&h;
            }
            #pragma unroll
            for (int q = 0; q < 4; ++q)
                *(uint4*)(smem + bufoff + aoff[q]) =
                    make_uint4(hv[4*q], hv[4*q+1], hv[4*q+2], hv[4*q+3]);
        } else {
            const unsigned char* gsrc = g_B + (size_t)c * B_BYTES;
            const int t2 = tid - 128;
            #pragma unroll
            for (int j = 0; j < 8; ++j) {
                uint32_t idx = (uint32_t)(t2 + j * 128) * 16u;
                CP_ASYNC16(sb + bufoff + A_BYTES + idx, gsrc + idx);
            }
            CP_COMMIT();
        }
    };
    auto mmaChunk = [&](uint32_t bufoff) {
        const uint32_t AH = sb + bufoff, BP = AH + A_BYTES;
        #pragma unroll
        for (int ks = 0; ks < 4; ++ks) {
            const uint32_t kxA = (uint32_t)(((ks << 1) | kbA) ^ mswA) << 4;
            const uint32_t kxB = (uint32_t)(((ks << 1) | kbB) ^ nswB) << 4;
            uint32_t a0[4], a1[4], bf[8];
            ldsm4(a0[0], a0[1], a0[2], a0[3], AH + moA0 + kxA);
            ldsm4(a1[0], a1[1], a1[2], a1[3], AH + moA1 + kxA);
            ldsm4(bf[0], bf[1], bf[2], bf[3], BP + noB0 + kxB);
            ldsm4(bf[4], bf[5], bf[6], bf[7], BP + noB1 + kxB);
            #pragma unroll
            for (int nt = 0; nt < 4; ++nt) {
                mma16816(acc[0][nt], a0, &bf[nt * 2]);
                mma16816(acc[1][nt], a1, &bf[nt * 2]);
            }
        }
    };

    // ---- prologue ----
    produce(0, SM_BUF0);
    CP_WAIT0();
    __syncthreads();

    // ---- main pipelined loop ----
    for (int c = 0; c < NCHUNKS; ++c) {
        const uint32_t bufc = (c & 1) ? SM_BUF1 : SM_BUF0;
        const uint32_t bufn = (c & 1) ? SM_BUF0 : SM_BUF1;
        if (c < NCHUNKS - 1) produce(c + 1, bufn);
        mmaChunk(bufc);
        if (c < NCHUNKS - 1) CP_WAIT0();
        __syncthreads();
    }

    // ---- epilogue: acc -> f32 smem tile -> bias + LN -> gmem ----
    {
        float* tile = (float*)smem;                  // 64 x 132 f32 = 33792B
        const int g4 = lane >> 2, t4 = lane & 3;
        #pragma unroll
        for (int mt = 0; mt < 2; ++mt) {
            #pragma unroll
            for (int nt = 0; nt < 4; ++nt) {
                int rowm = m0w + mt * 16 + g4;
                int col  = nb + nt * 8 + 2 * t4;
                *(float2*)&tile[rowm * EPI_STRIDE + col] =
                    make_float2(acc[mt][nt][0], acc[mt][nt][1]);
                *(float2*)&tile[(rowm + 8) * EPI_STRIDE + col] =
                    make_float2(acc[mt][nt][2], acc[mt][nt][3]);
            }
        }
    }
    __syncthreads();

    if (tid < 64) {
        const float* tile = (const float*)smem;
        const float* bS  = (const float*)(smem + SM_PAR);
        const float* gS  = bS + 128;
        const float* btS = bS + 256;
        float v[128];
        float s = 0.f, q = 0.f;
        #pragma unroll
        for (int j4 = 0; j4 < 32; ++j4) {
            float4 t4v = *(const float4*)&tile[tid * EPI_STRIDE + j4 * 4];
            float a0 = t4v.x + bS[j4*4+0], a1 = t4v.y + bS[j4*4+1];
            float a2 = t4v.z + bS[j4*4+2], a3 = t4v.w + bS[j4*4+3];
            v[j4*4+0] = a0; v[j4*4+1] = a1; v[j4*4+2] = a2; v[j4*4+3] = a3;
            s += (a0 + a1) + (a2 + a3);
            q += a0*a0 + a1*a1 + a2*a2 + a3*a3;
        }
        float mu  = s * (1.0f / 128.0f);
        float var = q * (1.0f / 128.0f) - mu * mu;
        float rs  = rsqrtf(var + 1e-5f);
        float4* op = (float4*)(Out + (size_t)(n0blk + tid) * DIM_O);
        #pragma unroll
        for (int j4 = 0; j4 < 32; ++j4) {
            float4 o;
            o.x = (v[j4*4+0] - mu) * rs * gS[j4*4+0] + btS[j4*4+0];
            o.y = (v[j4*4+1] - mu) * rs * gS[j4*4+1] + btS[j4*4+1];
            o.z = (v[j4*4+2] - mu) * rs * gS[j4*4+2] + btS[j4*4+2];
            o.w = (v[j4*4+3] - mu) * rs * gS[j4*4+3] + btS[j4*4+3];
            op[j4] = o;
        }
    }
}

// ---------------------------------------------------------------------------
extern "C" void kernel_launch(void* const* d_in, const int* in_sizes, int n_in,
                              void* d_out, int out_size) {
    const float* x     = (const float*)d_in[0];
    const float* cosA  = (const float*)d_in[1];
    const float* sinA  = (const float*)d_in[2];
    const float* bias  = (const float*)d_in[3];
    const float* gamma = (const float*)d_in[4];
    const float* beta  = (const float*)d_in[5];
    float* out = (float*)d_out;

    const int N = in_sizes[0] / DIM_I;

    cudaFuncSetAttribute(fkan_hmma, cudaFuncAttributeMaxDynamicSharedMemorySize,
                         SMEM_TOTAL);

    const int tw = DIM_O * DIM_I * DIM_G;
    prep_weights<<<(tw + 255) / 256, 256>>>(cosA, sinA);
    fkan_hmma<<<N / 64, 256, SMEM_TOTAL>>>(x, bias, gamma, beta, out);
}

// round 6
// speedup vs baseline: 6.6767x; 1.0785x over previous
#include <cuda_runtime.h>
#include <cuda_fp16.h>
#include <stdint.h>

#define DIM_I 128
#define DIM_G 16
#define DIM_O 128
#define NCHUNKS 64               // chunk = 2 input dims = 64 k-steps
#define B_BYTES 16384            // 128 o-rows x 64 fp16 (128B rows)
#define A_BYTES 8192             // 64 rows x 64 fp16
#define ST_BYTES (A_BYTES + B_BYTES)         // 24576 per stage
#define NSTAGES 3
#define SM_X    (NSTAGES * ST_BYTES)         // 73728 ; X tile 64 x 129 f32
#define X_STRIDE 129
#define SM_PAR  (SM_X + 64 * X_STRIDE * 4)   // 106752 ; bias|gamma|beta
#define SMEM_TOTAL (SM_PAR + 3 * 128 * 4)    // 108288
#define EPI_STRIDE 132

// Pre-converted fp16 weights, pre-swizzled, one plane per chunk
__device__ __align__(16) unsigned char g_B[NCHUNKS * B_BYTES];   // 1 MB

__device__ __forceinline__ uint32_t smem_u32(const void* p) {
    uint32_t a;
    asm("{ .reg .u64 t; cvta.to.shared.u64 t, %1; cvt.u32.u64 %0, t; }" : "=r"(a) : "l"(p));
    return a;
}
__device__ __forceinline__ void ldsm4(uint32_t& r0, uint32_t& r1, uint32_t& r2,
                                      uint32_t& r3, uint32_t a) {
    asm volatile("ldmatrix.sync.aligned.m8n8.x4.shared.b16 {%0,%1,%2,%3}, [%4];"
                 : "=r"(r0), "=r"(r1), "=r"(r2), "=r"(r3) : "r"(a));
}
__device__ __forceinline__ void mma16816(float* d, const uint32_t* a, const uint32_t* b) {
    asm volatile(
        "mma.sync.aligned.m16n8k16.row.col.f32.f16.f16.f32 "
        "{%0,%1,%2,%3}, {%4,%5,%6,%7}, {%8,%9}, {%0,%1,%2,%3};"
        : "+f"(d[0]), "+f"(d[1]), "+f"(d[2]), "+f"(d[3])
        : "r"(a[0]), "r"(a[1]), "r"(a[2]), "r"(a[3]), "r"(b[0]), "r"(b[1]));
}
#define CP_ASYNC16(dst, src) \
    asm volatile("cp.async.cg.shared.global [%0], [%1], 16;" :: "r"(dst), "l"(src) : "memory")
#define CP_COMMIT()    asm volatile("cp.async.commit_group;" ::: "memory")
#define CP_WAIT(n)     asm volatile("cp.async.wait_group %0;" :: "n"(n) : "memory")

// ---------------------------------------------------------------------------
// Prep: weights -> fp16, {cos,sin} adjacent in k, swizzled 128B rows per chunk.
// k_local = (i&1)*32 + 2g + {0=cos,1=sin}; chunk = i>>1.
// ---------------------------------------------------------------------------
__global__ void prep_weights(const float* __restrict__ cosA,
                             const float* __restrict__ sinA) {
    int t = blockIdx.x * blockDim.x + threadIdx.x;   // over O*I*G = 262144
    if (t >= DIM_O * DIM_I * DIM_G) return;
    int o = t >> 11, rem = t & 2047, i = rem >> 4, g = rem & 15;
    half2 w = __floats2half2_rn(cosA[t], sinA[t]);   // lo=cos, hi=sin
    int chunk = i >> 1;
    int kl = (i & 1) * 32 + 2 * g;
    int cidx = kl >> 3;
    uint32_t off = (uint32_t)(o * 128 + ((cidx ^ (o & 7)) << 4) + (kl & 7) * 2);
    *(uint32_t*)(g_B + (size_t)chunk * B_BYTES + off) = *(uint32_t*)&w;
}

// ---------------------------------------------------------------------------
// Main: BM=64, BN=128, 256 threads, 2 CTAs/SM. Warps split 2m x 2n x 2k
// (k-split partials, reduced in epilogue). 3-stage pipeline, X staged in smem.
// ---------------------------------------------------------------------------
__global__ __launch_bounds__(256, 2)
void fkan_hmma(const float* __restrict__ X,
               const float* __restrict__ bias,
               const float* __restrict__ gamma,
               const float* __restrict__ beta,
               float* __restrict__ Out) {
    extern __shared__ unsigned char smem[];
    const uint32_t sb = smem_u32(smem);
    const int tid = threadIdx.x, w = tid >> 5, lane = tid & 31;
    const int n0blk = blockIdx.x * 64;
    float* xs = (float*)(smem + SM_X);

    if (tid < 128) {
        ((float*)(smem + SM_PAR))[tid]       = bias[tid];
        ((float*)(smem + SM_PAR))[128 + tid] = gamma[tid];
        ((float*)(smem + SM_PAR))[256 + tid] = beta[tid];
    }
    // ---- stage X tile: 64 rows x 128 f32, padded stride 129 ----
    {
        const float* src = X + (size_t)n0blk * DIM_I;
        #pragma unroll
        for (int it = 0; it < 32; ++it) {
            int idx = tid + it * 256;                // 0..8191
            xs[(idx >> 7) * X_STRIDE + (idx & 127)] = src[idx];
        }
    }

    // ---- producer roles: threads 0-127 gen A, 128-255 cp.async B ----
    const int row = tid & 63, hd = (tid >> 6) & 1;   // meaningful for tid<128
    uint32_t aoff[4];
    #pragma unroll
    for (int q = 0; q < 4; ++q)
        aoff[q] = (uint32_t)(row * 128 + (((hd * 4 + q) ^ (row & 7)) << 4));

    // ---- mma constants: 8 warps as ki(2) x mi(2) x ni(2), tile 32m x 64n x 32k ----
    const int ki = w >> 2, mi = (w >> 1) & 1, ni = w & 1;
    const int r8 = lane & 7, bsel = lane >> 3;
    const int kbA = bsel >> 1;
    const int mr0 = mi * 32 + r8 + ((bsel & 1) << 3);
    const uint32_t moA0 = (uint32_t)(mr0 * 128), moA1 = moA0 + 16 * 128;
    const uint32_t mswA = (uint32_t)(mr0 & 7);
    const int kbB = bsel & 1;
    const int nrb = ni * 64 + r8 + ((bsel >> 1) << 3);
    const uint32_t nswB = (uint32_t)(nrb & 7);
    uint32_t noB[4];
    #pragma unroll
    for (int t = 0; t < 4; ++t) noB[t] = (uint32_t)((nrb + 16 * t) * 128);

    float acc[2][8][4];
    #pragma unroll
    for (int mt = 0; mt < 2; ++mt)
        #pragma unroll
        for (int nt = 0; nt < 8; ++nt)
            #pragma unroll
            for (int j = 0; j < 4; ++j) acc[mt][nt][j] = 0.f;

    auto produce = [&](int c) {
        const uint32_t bufoff = (uint32_t)(c % NSTAGES) * ST_BYTES;
        if (tid < 128) {
            const int dim = 2 * c + hd;
            float xv = xs[row * X_STRIDE + dim];
            float s1, c1;
            __sincosf(xv, &s1, &c1);
            uint32_t hv[16];
            float cg = c1, sg = s1;
            #pragma unroll
            for (int g = 0; g < 16; ++g) {
                if (g) {
                    float cn = fmaf(cg, c1, -(sg * s1));
                    float sn = fmaf(sg, c1,  (cg * s1));
                    cg = cn; sg = sn;
                }
                half2 h = __floats2half2_rn(cg, sg);
                hv[g] = *(uint32_t*)&h;
            }
            #pragma unroll
            for (int q = 0; q < 4; ++q)
                *(uint4*)(smem + bufoff + aoff[q]) =
                    make_uint4(hv[4*q], hv[4*q+1], hv[4*q+2], hv[4*q+3]);
        } else {
            const unsigned char* gsrc = g_B + (size_t)c * B_BYTES;
            const int t2 = tid - 128;
            #pragma unroll
            for (int j = 0; j < 8; ++j) {
                uint32_t idx = (uint32_t)(t2 + j * 128) * 16u;
                CP_ASYNC16(sb + bufoff + A_BYTES + idx, gsrc + idx);
            }
            CP_COMMIT();
        }
    };
    auto mmaChunk = [&](int c) {
        const uint32_t bufoff = (uint32_t)(c % NSTAGES) * ST_BYTES;
        const uint32_t AH = sb + bufoff, BP = AH + A_BYTES;
        #pragma unroll
        for (int ks = 0; ks < 2; ++ks) {
            const int kq = ki * 4 + ks * 2;               // 16B-chunk base in k
            const uint32_t kxA = (uint32_t)((kq | kbA) ^ mswA) << 4;
            const uint32_t kxB = (uint32_t)((kq | kbB) ^ nswB) << 4;
            uint32_t a0[4], a1[4], bf[16];
            ldsm4(a0[0], a0[1], a0[2], a0[3], AH + moA0 + kxA);
            ldsm4(a1[0], a1[1], a1[2], a1[3], AH + moA1 + kxA);
            #pragma unroll
            for (int t = 0; t < 4; ++t)
                ldsm4(bf[4*t], bf[4*t+1], bf[4*t+2], bf[4*t+3], BP + noB[t] + kxB);
            #pragma unroll
            for (int nt = 0; nt < 8; ++nt) {
                const uint32_t* b = &bf[(nt >> 1) * 4 + (nt & 1) * 2];
                mma16816(acc[0][nt], a0, b);
                mma16816(acc[1][nt], a1, b);
            }
        }
    };

    // ---- prologue: X barrier, then stage chunks 0,1 ----
    __syncthreads();          // X + params visible
    produce(0);
    produce(1);
    CP_WAIT(1);
    __syncthreads();

    // ---- main 3-stage pipelined loop ----
    for (int c = 0; c < NCHUNKS; ++c) {
        if (c < NCHUNKS - 2) {
            produce(c + 2);
            mmaChunk(c);
            CP_WAIT(1);
        } else {
            mmaChunk(c);
            CP_WAIT(0);
        }
        __syncthreads();
    }

    // ---- epilogue: k-split reduction into f32 smem tile, bias + LN ----
    {
        float* tile = (float*)smem;                  // 64 x 132 f32 = 33.8KB
        const int g4 = lane >> 2, t4 = lane & 3;
        if (ki == 0) {
            #pragma unroll
            for (int mt = 0; mt < 2; ++mt)
                #pragma unroll
                for (int nt = 0; nt < 8; ++nt) {
                    int rowm = mi * 32 + mt * 16 + g4;
                    int col  = ni * 64 + nt * 8 + 2 * t4;
                    *(float2*)&tile[rowm * EPI_STRIDE + col] =
                        make_float2(acc[mt][nt][0], acc[mt][nt][1]);
                    *(float2*)&tile[(rowm + 8) * EPI_STRIDE + col] =
                        make_float2(acc[mt][nt][2], acc[mt][nt][3]);
                }
        }
        __syncthreads();
        if (ki == 1) {
            #pragma unroll
            for (int mt = 0; mt < 2; ++mt)
                #pragma unroll
                for (int nt = 0; nt < 8; ++nt) {
                    int rowm = mi * 32 + mt * 16 + g4;
                    int col  = ni * 64 + nt * 8 + 2 * t4;
                    float2* p0 = (float2*)&tile[rowm * EPI_STRIDE + col];
                    float2* p1 = (float2*)&tile[(rowm + 8) * EPI_STRIDE + col];
                    float2 v0 = *p0, v1 = *p1;
                    v0.x += acc[mt][nt][0]; v0.y += acc[mt][nt][1];
                    v1.x += acc[mt][nt][2]; v1.y += acc[mt][nt][3];
                    *p0 = v0; *p1 = v1;
                }
        }
    }
    __syncthreads();

    if (tid < 64) {
        const float* tile = (const float*)smem;
        const float* bS  = (const float*)(smem + SM_PAR);
        const float* gS  = bS + 128;
        const float* btS = bS + 256;
        float v[128];
        float s = 0.f, q = 0.f;
        #pragma unroll
        for (int j4 = 0; j4 < 32; ++j4) {
            float4 t4v = *(const float4*)&tile[tid * EPI_STRIDE + j4 * 4];
            float a0 = t4v.x + bS[j4*4+0], a1 = t4v.y + bS[j4*4+1];
            float a2 = t4v.z + bS[j4*4+2], a3 = t4v.w + bS[j4*4+3];
            v[j4*4+0] = a0; v[j4*4+1] = a1; v[j4*4+2] = a2; v[j4*4+3] = a3;
            s += (a0 + a1) + (a2 + a3);
            q += a0*a0 + a1*a1 + a2*a2 + a3*a3;
        }
        float mu  = s * (1.0f / 128.0f);
        float var = q * (1.0f / 128.0f) - mu * mu;
        float rs  = rsqrtf(var + 1e-5f);
        float4* op = (float4*)(Out + (size_t)(n0blk + tid) * DIM_O);
        #pragma unroll
        for (int j4 = 0; j4 < 32; ++j4) {
            float4 o;
            o.x = (v[j4*4+0] - mu) * rs * gS[j4*4+0] + btS[j4*4+0];
            o.y = (v[j4*4+1] - mu) * rs * gS[j4*4+1] + btS[j4*4+1];
            o.z = (v[j4*4+2] - mu) * rs * gS[j4*4+2] + btS[j4*4+2];
            o.w = (v[j4*4+3] - mu) * rs * gS[j4*4+3] + btS[j4*4+3];
            op[j4] = o;
        }
    }
}

// ---------------------------------------------------------------------------
extern "C" void kernel_launch(void* const* d_in, const int* in_sizes, int n_in,
                              void* d_out, int out_size) {
    const float* x     = (const float*)d_in[0];
    const float* cosA  = (const float*)d_in[1];
    const float* sinA  = (const float*)d_in[2];
    const float* bias  = (const float*)d_in[3];
    const float* gamma = (const float*)d_in[4];
    const float* beta  = (const float*)d_in[5];
    float* out = (float*)d_out;

    const int N = in_sizes[0] / DIM_I;

    cudaFuncSetAttribute(fkan_hmma, cudaFuncAttributeMaxDynamicSharedMemorySize,
                         SMEM_TOTAL);

    const int tw = DIM_O * DIM_I * DIM_G;
    prep_weights<<<(tw + 255) / 256, 256>>>(cosA, sinA);
    fkan_hmma<<<N / 64, 256, SMEM_TOTAL>>>(x, bias, gamma, beta, out);
}

// round 7
// speedup vs baseline: 7.5848x; 1.1360x over previous
#include <cuda_runtime.h>
#include <cuda_fp16.h>
#include <stdint.h>

#define DIM_I 128
#define DIM_G 16
#define DIM_O 128
#define NCHUNKS 32               // chunk = 4 input dims = 128 k-steps
#define A_SP 8192                // A sub-plane: 64 rows x 64 fp16
#define B_SP 16384               // B sub-plane: 128 rows x 64 fp16
#define A_BYTES 16384            // 2 sub-planes
#define ST_BYTES 49152           // A0|A1|B0|B1
#define SM_PAR  (2 * ST_BYTES)   // 98304 ; bias|gamma|beta
#define SMEM_TOTAL (SM_PAR + 3 * 128 * 4)   // 99840
#define EPI_STRIDE 132

// Pre-converted fp16 weights, pre-swizzled, 16KB per 64-k sub-chunk (64 of them)
__device__ __align__(16) unsigned char g_B[64 * 16384];   // 1 MB

__device__ __forceinline__ uint32_t smem_u32(const void* p) {
    uint32_t a;
    asm("{ .reg .u64 t; cvta.to.shared.u64 t, %1; cvt.u32.u64 %0, t; }" : "=r"(a) : "l"(p));
    return a;
}
__device__ __forceinline__ void ldsm4(uint32_t& r0, uint32_t& r1, uint32_t& r2,
                                      uint32_t& r3, uint32_t a) {
    asm volatile("ldmatrix.sync.aligned.m8n8.x4.shared.b16 {%0,%1,%2,%3}, [%4];"
                 : "=r"(r0), "=r"(r1), "=r"(r2), "=r"(r3) : "r"(a));
}
__device__ __forceinline__ void mma16816(float* d, const uint32_t* a, const uint32_t* b) {
    asm volatile(
        "mma.sync.aligned.m16n8k16.row.col.f32.f16.f16.f32 "
        "{%0,%1,%2,%3}, {%4,%5,%6,%7}, {%8,%9}, {%0,%1,%2,%3};"
        : "+f"(d[0]), "+f"(d[1]), "+f"(d[2]), "+f"(d[3])
        : "r"(a[0]), "r"(a[1]), "r"(a[2]), "r"(a[3]), "r"(b[0]), "r"(b[1]));
}
#define CP_ASYNC16(dst, src) \
    asm volatile("cp.async.cg.shared.global [%0], [%1], 16;" :: "r"(dst), "l"(src) : "memory")
#define CP_COMMIT()    asm volatile("cp.async.commit_group;" ::: "memory")
#define CP_WAIT0()     asm volatile("cp.async.wait_group 0;" ::: "memory")
// named barriers: full0=1, full1=2, empty0=3, empty1=4, consumer-only=5
#define BAR_SYNC(id, cnt)   asm volatile("bar.sync %0, %1;"   :: "r"(id), "r"(cnt) : "memory")
#define BAR_ARRIVE(id, cnt) asm volatile("bar.arrive %0, %1;" :: "r"(id), "r"(cnt) : "memory")

// ---------------------------------------------------------------------------
// Prep: weights -> fp16, {cos,sin} adjacent in k, swizzled 128B rows.
// sub-chunk sc = i>>1 (64 of them); k_local = (i&1)*32 + 2g + {0=cos,1=sin}.
// ---------------------------------------------------------------------------
__global__ void prep_weights(const float* __restrict__ cosA,
                             const float* __restrict__ sinA) {
    int t = blockIdx.x * blockDim.x + threadIdx.x;   // over O*I*G = 262144
    if (t >= DIM_O * DIM_I * DIM_G) return;
    int o = t >> 11, rem = t & 2047, i = rem >> 4, g = rem & 15;
    half2 w = __floats2half2_rn(cosA[t], sinA[t]);   // lo=cos, hi=sin
    int sc = i >> 1;
    int kl = (i & 1) * 32 + 2 * g;
    int cidx = kl >> 3;
    uint32_t off = (uint32_t)(o * 128 + ((cidx ^ (o & 7)) << 4) + (kl & 7) * 2);
    *(uint32_t*)(g_B + (size_t)sc * 16384 + off) = *(uint32_t*)&w;
}

// ---------------------------------------------------------------------------
// Main: warp-specialized. Threads 0-127 = consumers (4 warps, 32m x 64n tiles,
// full 128-k chunks). Threads 128-255 = producers (trig gen A + cp.async B).
// Named-barrier full/empty handoff, 2 stages. Fused bias + LayerNorm epilogue.
// ---------------------------------------------------------------------------
__global__ __launch_bounds__(256, 2)
void fkan_ws(const float* __restrict__ X,
             const float* __restrict__ bias,
             const float* __restrict__ gamma,
             const float* __restrict__ beta,
             float* __restrict__ Out) {
    extern __shared__ unsigned char smem[];
    const uint32_t sb = smem_u32(smem);
    const int tid = threadIdx.x, w = tid >> 5, lane = tid & 31;
    const int n0blk = blockIdx.x * 64;

    if (tid < 128) {
        ((float*)(smem + SM_PAR))[tid]       = bias[tid];
        ((float*)(smem + SM_PAR))[128 + tid] = gamma[tid];
        ((float*)(smem + SM_PAR))[256 + tid] = beta[tid];
    }

    if (tid >= 128) {
        // ================= PRODUCER (threads 128..255) =================
        const int p = tid - 128;
        const int row = p & 63, hd = (p >> 6) & 1;
        uint32_t aoff[4];
        #pragma unroll
        for (int q = 0; q < 4; ++q)
            aoff[q] = (uint32_t)(row * 128 + (((hd * 4 + q) ^ (row & 7)) << 4));
        const float* xrow = X + (size_t)(n0blk + row) * DIM_I;

        float4 xq = *(const float4*)xrow;            // chunk 0 dims 0..3
        for (int c = 0; c < NCHUNKS; ++c) {
            const int s = c & 1;
            unsigned char* stgp = smem + s * ST_BYTES;
            const uint32_t stg = sb + (uint32_t)(s * ST_BYTES);
            if (c >= 2) BAR_SYNC(3 + s, 256);        // wait empty[s]
            float4 xn;
            if (c + 1 < NCHUNKS)
                xn = *(const float4*)(xrow + 4 * (c + 1));   // prefetch
            // ---- gen A: 2 sub-planes, one dim each ----
            #pragma unroll
            for (int sp = 0; sp < 2; ++sp) {
                float xv = ((const float*)&xq)[sp * 2 + hd];
                float s1, c1;
                __sincosf(xv, &s1, &c1);
                uint32_t hv[16];
                float cg = c1, sg = s1;
                #pragma unroll
                for (int g = 0; g < 16; ++g) {
                    if (g) {
                        float cn = fmaf(cg, c1, -(sg * s1));
                        float sn = fmaf(sg, c1,  (cg * s1));
                        cg = cn; sg = sn;
                    }
                    half2 h = __floats2half2_rn(cg, sg);
                    hv[g] = *(uint32_t*)&h;
                }
                #pragma unroll
                for (int q = 0; q < 4; ++q)
                    *(uint4*)(stgp + sp * A_SP + aoff[q]) =
                        make_uint4(hv[4*q], hv[4*q+1], hv[4*q+2], hv[4*q+3]);
            }
            // ---- cp.async B: 32KB contiguous (sub-chunks 2c, 2c+1) ----
            const unsigned char* gsrc = g_B + (size_t)c * 32768;
            #pragma unroll
            for (int j = 0; j < 16; ++j) {
                uint32_t idx = (uint32_t)(p + j * 128) * 16u;
                CP_ASYNC16(stg + A_BYTES + idx, gsrc + idx);
            }
            CP_COMMIT();
            CP_WAIT0();
            BAR_ARRIVE(1 + s, 256);                  // full[s]
            xq = xn;
        }
        return;                                      // producers exit
    }

    // ================= CONSUMER (threads 0..127, 4 warps) =================
    const int mi = w & 1, ni = w >> 1;
    const int r8 = lane & 7, bsel = lane >> 3;
    const int kbA = bsel >> 1;
    const int mr0 = mi * 32 + r8 + ((bsel & 1) << 3);
    const uint32_t moA0 = (uint32_t)(mr0 * 128), moA1 = moA0 + 16 * 128;
    const int kbB = bsel & 1;
    const int nrb = ni * 64 + r8 + ((bsel >> 1) << 3);
    uint32_t noB[4];
    #pragma unroll
    for (int t = 0; t < 4; ++t) noB[t] = (uint32_t)((nrb + 16 * t) * 128);
    uint32_t kxA[4], kxB[4];
    #pragma unroll
    for (int ks = 0; ks < 4; ++ks) {
        kxA[ks] = (uint32_t)((((ks << 1) | kbA) ^ (mr0 & 7)) << 4);
        kxB[ks] = (uint32_t)((((ks << 1) | kbB) ^ (nrb & 7)) << 4);
    }

    float acc[2][8][4];
    #pragma unroll
    for (int mt = 0; mt < 2; ++mt)
        #pragma unroll
        for (int nt = 0; nt < 8; ++nt)
            #pragma unroll
            for (int j = 0; j < 4; ++j) acc[mt][nt][j] = 0.f;

    for (int c = 0; c < NCHUNKS; ++c) {
        const int s = c & 1;
        const uint32_t stg = sb + (uint32_t)(s * ST_BYTES);
        BAR_SYNC(1 + s, 256);                        // wait full[s]
        #pragma unroll
        for (int sp = 0; sp < 2; ++sp) {
            const uint32_t AH = stg + (uint32_t)(sp * A_SP);
            const uint32_t BP = stg + A_BYTES + (uint32_t)(sp * B_SP);
            #pragma unroll
            for (int ks = 0; ks < 4; ++ks) {
                uint32_t a0[4], a1[4], bf[16];
                ldsm4(a0[0], a0[1], a0[2], a0[3], AH + moA0 + kxA[ks]);
                ldsm4(a1[0], a1[1], a1[2], a1[3], AH + moA1 + kxA[ks]);
                #pragma unroll
                for (int t = 0; t < 4; ++t)
                    ldsm4(bf[4*t], bf[4*t+1], bf[4*t+2], bf[4*t+3],
                          BP + noB[t] + kxB[ks]);
                #pragma unroll
                for (int nt = 0; nt < 8; ++nt) {
                    const uint32_t* b = &bf[(nt >> 1) * 4 + (nt & 1) * 2];
                    mma16816(acc[0][nt], a0, b);
                    mma16816(acc[1][nt], a1, b);
                }
            }
        }
        BAR_ARRIVE(3 + s, 256);                      // empty[s]
    }

    // ---- epilogue: acc -> f32 smem tile -> bias + LN -> gmem ----
    {
        float* tile = (float*)smem;                  // 64 x 132 f32 = 33792B
        const int g4 = lane >> 2, t4 = lane & 3;
        #pragma unroll
        for (int mt = 0; mt < 2; ++mt)
            #pragma unroll
            for (int nt = 0; nt < 8; ++nt) {
                int rowm = mi * 32 + mt * 16 + g4;
                int col  = ni * 64 + nt * 8 + 2 * t4;
                *(float2*)&tile[rowm * EPI_STRIDE + col] =
                    make_float2(acc[mt][nt][0], acc[mt][nt][1]);
                *(float2*)&tile[(rowm + 8) * EPI_STRIDE + col] =
                    make_float2(acc[mt][nt][2], acc[mt][nt][3]);
            }
    }
    BAR_SYNC(5, 128);                                // consumers only

    if (tid < 64) {
        const float* tile = (const float*)smem;
        const float* bS  = (const float*)(smem + SM_PAR);
        const float* gS  = bS + 128;
        const float* btS = bS + 256;
        float v[128];
        float s = 0.f, q = 0.f;
        #pragma unroll
        for (int j4 = 0; j4 < 32; ++j4) {
            float4 t4v = *(const float4*)&tile[tid * EPI_STRIDE + j4 * 4];
            float a0 = t4v.x + bS[j4*4+0], a1 = t4v.y + bS[j4*4+1];
            float a2 = t4v.z + bS[j4*4+2], a3 = t4v.w + bS[j4*4+3];
            v[j4*4+0] = a0; v[j4*4+1] = a1; v[j4*4+2] = a2; v[j4*4+3] = a3;
            s += (a0 + a1) + (a2 + a3);
            q += a0*a0 + a1*a1 + a2*a2 + a3*a3;
        }
        float mu  = s * (1.0f / 128.0f);
        float var = q * (1.0f / 128.0f) - mu * mu;
        float rs  = rsqrtf(var + 1e-5f);
        float4* op = (float4*)(Out + (size_t)(n0blk + tid) * DIM_O);
        #pragma unroll
        for (int j4 = 0; j4 < 32; ++j4) {
            float4 o;
            o.x = (v[j4*4+0] - mu) * rs * gS[j4*4+0] + btS[j4*4+0];
            o.y = (v[j4*4+1] - mu) * rs * gS[j4*4+1] + btS[j4*4+1];
            o.z = (v[j4*4+2] - mu) * rs * gS[j4*4+2] + btS[j4*4+2];
            o.w = (v[j4*4+3] - mu) * rs * gS[j4*4+3] + btS[j4*4+3];
            op[j4] = o;
        }
    }
}

// ---------------------------------------------------------------------------
extern "C" void kernel_launch(void* const* d_in, const int* in_sizes, int n_in,
                              void* d_out, int out_size) {
    const float* x     = (const float*)d_in[0];
    const float* cosA  = (const float*)d_in[1];
    const float* sinA  = (const float*)d_in[2];
    const float* bias  = (const float*)d_in[3];
    const float* gamma = (const float*)d_in[4];
    const float* beta  = (const float*)d_in[5];
    float* out = (float*)d_out;

    const int N = in_sizes[0] / DIM_I;

    cudaFuncSetAttribute(fkan_ws, cudaFuncAttributeMaxDynamicSharedMemorySize,
                         SMEM_TOTAL);

    const int tw = DIM_O * DIM_I * DIM_G;
    prep_weights<<<(tw + 255) / 256, 256>>>(cosA, sinA);
    fkan_ws<<<N / 64, 256, SMEM_TOTAL>>>(x, bias, gamma, beta, out);
}